// round 2
// baseline (speedup 1.0000x reference)
#include <cuda_runtime.h>
#include <math.h>

#define B_ 8
#define M_ 1024
#define D_ 1024
#define H_ 16
#define F_ 4096
#define NLAYERS 4
#define DK_ 64
#define ROWS (B_*M_)   // 8192

// ---------------- scratch (device globals; no allocation) ----------------
__device__ float g_x  [ROWS * D_];
__device__ float g_q  [ROWS * D_];
__device__ float g_k  [ROWS * D_];
__device__ float g_v  [ROWS * D_];
__device__ float g_o  [ROWS * D_];
__device__ float g_ffn[ROWS * F_];   // also reused as attention output buffer

__device__ __forceinline__ float gelu_exact(float x) {
    return 0.5f * x * (1.0f + erff(x * 0.70710678118654752f));
}

// ---------------- SGEMM: C = A(MxK) @ W(KxN) + bias, optional GELU -------
// 128x128 tile, BK=16, 256 threads, 8x8 microtile (split 4 + 64-offset 4)
template<bool GELU>
__global__ __launch_bounds__(256) void sgemm_bias(
    const float* __restrict__ A, const float* __restrict__ W,
    const float* __restrict__ bias, float* __restrict__ C,
    int Kdim, int Ncols)
{
    __shared__ float As[16][132];
    __shared__ float Bs[16][128];

    const int tid = threadIdx.x;
    const int m0 = blockIdx.y * 128;
    const int n0 = blockIdx.x * 128;
    const int ty = tid >> 4;       // 0..15
    const int tx = tid & 15;       // 0..15

    float acc[8][8];
#pragma unroll
    for (int i = 0; i < 8; i++)
#pragma unroll
        for (int j = 0; j < 8; j++) acc[i][j] = 0.0f;

    const int ar = tid >> 2;       // 0..63
    const int ac = tid & 3;        // 0..3
    const int br = tid >> 5;       // 0..7
    const int bc = tid & 31;       // 0..31

    const float* Aload = A + (size_t)(m0 + ar) * Kdim + ac * 4;
    const float* Bload = W + (size_t)br * Ncols + n0 + bc * 4;

    for (int k0 = 0; k0 < Kdim; k0 += 16) {
#pragma unroll
        for (int p = 0; p < 2; p++) {
            float4 av = *(const float4*)(Aload + (size_t)(p * 64) * Kdim + k0);
            As[ac * 4 + 0][ar + p * 64] = av.x;
            As[ac * 4 + 1][ar + p * 64] = av.y;
            As[ac * 4 + 2][ar + p * 64] = av.z;
            As[ac * 4 + 3][ar + p * 64] = av.w;
        }
#pragma unroll
        for (int p = 0; p < 2; p++) {
            float4 bv = *(const float4*)(Bload + (size_t)(k0 + p * 8) * Ncols);
            *(float4*)&Bs[br + p * 8][bc * 4] = bv;
        }
        __syncthreads();

#pragma unroll
        for (int kk = 0; kk < 16; kk++) {
            float a[8], bb[8];
            *(float4*)&a[0]  = *(const float4*)&As[kk][ty * 4];
            *(float4*)&a[4]  = *(const float4*)&As[kk][64 + ty * 4];
            *(float4*)&bb[0] = *(const float4*)&Bs[kk][tx * 4];
            *(float4*)&bb[4] = *(const float4*)&Bs[kk][64 + tx * 4];
#pragma unroll
            for (int i = 0; i < 8; i++)
#pragma unroll
                for (int j = 0; j < 8; j++)
                    acc[i][j] = fmaf(a[i], bb[j], acc[i][j]);
        }
        __syncthreads();
    }

#pragma unroll
    for (int i = 0; i < 8; i++) {
        const int rr = m0 + ((i < 4) ? (ty * 4 + i) : (64 + ty * 4 + i - 4));
#pragma unroll
        for (int jg = 0; jg < 2; jg++) {
            const int cc = n0 + jg * 64 + tx * 4;
            float r0 = acc[i][jg * 4 + 0] + bias[cc + 0];
            float r1 = acc[i][jg * 4 + 1] + bias[cc + 1];
            float r2 = acc[i][jg * 4 + 2] + bias[cc + 2];
            float r3 = acc[i][jg * 4 + 3] + bias[cc + 3];
            if (GELU) {
                r0 = gelu_exact(r0); r1 = gelu_exact(r1);
                r2 = gelu_exact(r2); r3 = gelu_exact(r3);
            }
            *(float4*)&C[(size_t)rr * Ncols + cc] = make_float4(r0, r1, r2, r3);
        }
    }
}

// ---------------- Flash attention (fp32, online softmax) -----------------
// grid: (M/64, B*H), block 256. Each CTA: 64 q rows x DK=64, loops k tiles.
__global__ __launch_bounds__(256) void flash_attn(
    const float* __restrict__ q, const float* __restrict__ k,
    const float* __restrict__ v, const float* __restrict__ w,
    float* __restrict__ o)
{
    __shared__ float Qs[64][68];
    __shared__ float Kt[64][68];   // [d][kcol]
    __shared__ float Vs[64][68];
    __shared__ float Ps[64][68];

    const int b  = blockIdx.y >> 4;
    const int h  = blockIdx.y & 15;
    const int q0 = blockIdx.x * 64;
    const int tid = threadIdx.x;
    const int ty = tid >> 4;       // 0..15 -> rows ty*4..+3
    const int tx = tid & 15;       // 0..15 -> cols tx*4..+3
    const int hoff = h * DK_;

    const float* qbase = q + (size_t)b * M_ * D_ + hoff;
    const float* kbase = k + (size_t)b * M_ * D_ + hoff;
    const float* vbase = v + (size_t)b * M_ * D_ + hoff;
    const float* wbase = w + (size_t)b * M_;

    for (int idx = tid; idx < 64 * 64; idx += 256) {
        int r = idx >> 6, c = idx & 63;
        Qs[r][c] = qbase[(size_t)(q0 + r) * D_ + c];
    }

    float m_i[4], l_i[4], oacc[4][4];
#pragma unroll
    for (int i = 0; i < 4; i++) {
        m_i[i] = -1e30f; l_i[i] = 0.0f;
#pragma unroll
        for (int j = 0; j < 4; j++) oacc[i][j] = 0.0f;
    }
    __syncthreads();

    for (int kb = 0; kb < M_; kb += 64) {
        for (int idx = tid; idx < 64 * 64; idx += 256) {
            int r = idx >> 6, c = idx & 63;
            float kv = kbase[(size_t)(kb + r) * D_ + c];
            Kt[c][r] = kv;
            Vs[r][c] = vbase[(size_t)(kb + r) * D_ + c];
        }
        __syncthreads();

        float s[4][4];
#pragma unroll
        for (int i = 0; i < 4; i++)
#pragma unroll
            for (int j = 0; j < 4; j++) s[i][j] = 0.0f;

#pragma unroll 8
        for (int d = 0; d < 64; d++) {
            float a[4], bb[4];
#pragma unroll
            for (int i = 0; i < 4; i++) a[i] = Qs[ty * 4 + i][d];
#pragma unroll
            for (int j = 0; j < 4; j++) bb[j] = Kt[d][tx * 4 + j];
#pragma unroll
            for (int i = 0; i < 4; i++)
#pragma unroll
                for (int j = 0; j < 4; j++)
                    s[i][j] = fmaf(a[i], bb[j], s[i][j]);
        }

        float wj[4];
#pragma unroll
        for (int j = 0; j < 4; j++) wj[j] = wbase[kb + tx * 4 + j];
#pragma unroll
        for (int i = 0; i < 4; i++)
#pragma unroll
            for (int j = 0; j < 4; j++)
                s[i][j] = s[i][j] * 0.125f + wj[j];

#pragma unroll
        for (int i = 0; i < 4; i++) {
            float rmax = fmaxf(fmaxf(s[i][0], s[i][1]), fmaxf(s[i][2], s[i][3]));
#pragma unroll
            for (int off = 8; off > 0; off >>= 1)
                rmax = fmaxf(rmax, __shfl_xor_sync(0xffffffffu, rmax, off, 16));
            float mnew = fmaxf(m_i[i], rmax);
            float corr = __expf(m_i[i] - mnew);
            float rsum = 0.0f;
#pragma unroll
            for (int j = 0; j < 4; j++) {
                s[i][j] = __expf(s[i][j] - mnew);
                rsum += s[i][j];
            }
#pragma unroll
            for (int off = 8; off > 0; off >>= 1)
                rsum += __shfl_xor_sync(0xffffffffu, rsum, off, 16);
            l_i[i] = l_i[i] * corr + rsum;
            m_i[i] = mnew;
#pragma unroll
            for (int j = 0; j < 4; j++) oacc[i][j] *= corr;
#pragma unroll
            for (int j = 0; j < 4; j++) Ps[ty * 4 + i][tx * 4 + j] = s[i][j];
        }
        __syncthreads();

#pragma unroll 8
        for (int kk = 0; kk < 64; kk++) {
            float pr[4], vr[4];
#pragma unroll
            for (int i = 0; i < 4; i++) pr[i] = Ps[ty * 4 + i][kk];
#pragma unroll
            for (int j = 0; j < 4; j++) vr[j] = Vs[kk][tx * 4 + j];
#pragma unroll
            for (int i = 0; i < 4; i++)
#pragma unroll
                for (int j = 0; j < 4; j++)
                    oacc[i][j] = fmaf(pr[i], vr[j], oacc[i][j]);
        }
        __syncthreads();
    }

#pragma unroll
    for (int i = 0; i < 4; i++) {
        float inv = 1.0f / l_i[i];
        float4 ov = make_float4(oacc[i][0] * inv, oacc[i][1] * inv,
                                oacc[i][2] * inv, oacc[i][3] * inv);
        *(float4*)&o[(size_t)(b * M_ + q0 + ty * 4 + i) * D_ + hoff + tx * 4] = ov;
    }
}

// ---------------- fused residual add + LayerNorm -------------------------
__device__ __forceinline__ float block_sum256(float val, float* red) {
    const int lane = threadIdx.x & 31;
    const int wid  = threadIdx.x >> 5;
#pragma unroll
    for (int o = 16; o > 0; o >>= 1) val += __shfl_xor_sync(0xffffffffu, val, o);
    if (lane == 0) red[wid] = val;
    __syncthreads();
    float t = (threadIdx.x < 8) ? red[threadIdx.x] : 0.0f;
    if (wid == 0) {
#pragma unroll
        for (int o = 4; o > 0; o >>= 1) t += __shfl_xor_sync(0xffffffffu, t, o);
        if (lane == 0) red[0] = t;
    }
    __syncthreads();
    float r = red[0];
    __syncthreads();
    return r;
}

__global__ __launch_bounds__(256) void add_ln(
    const float* __restrict__ xin, const float* __restrict__ del,
    const float* __restrict__ g, const float* __restrict__ be,
    float* __restrict__ xout)
{
    __shared__ float red[8];
    const int row = blockIdx.x;
    const int tid = threadIdx.x;
    const float* xr = xin + (size_t)row * D_;
    const float* dr = del + (size_t)row * D_;

    float v[4];
    float s = 0.0f;
#pragma unroll
    for (int u = 0; u < 4; u++) {
        v[u] = xr[tid + u * 256] + dr[tid + u * 256];
        s += v[u];
    }
    float tot = block_sum256(s, red);
    float mu = tot * (1.0f / D_);
    float qs = 0.0f;
#pragma unroll
    for (int u = 0; u < 4; u++) {
        float d = v[u] - mu;
        qs += d * d;
    }
    float var = block_sum256(qs, red) * (1.0f / D_);
    float rstd = rsqrtf(var + 1e-5f);
#pragma unroll
    for (int u = 0; u < 4; u++) {
        int c = tid + u * 256;
        xout[(size_t)row * D_ + c] = (v[u] - mu) * rstd * g[c] + be[c];
    }
}

// ---------------- driver --------------------------------------------------
extern "C" void kernel_launch(void* const* d_in, const int* in_sizes, int n_in,
                              void* d_out, int out_size) {
    const float* embeds  = (const float*)d_in[0];
    const float* weights = (const float*)d_in[1];
    const float* Wq = (const float*)d_in[2];
    const float* bq = (const float*)d_in[3];
    const float* Wk = (const float*)d_in[4];
    const float* bk = (const float*)d_in[5];
    const float* Wv = (const float*)d_in[6];
    const float* bv = (const float*)d_in[7];
    const float* Wo = (const float*)d_in[8];
    const float* bo = (const float*)d_in[9];
    const float* W1 = (const float*)d_in[10];
    const float* b1 = (const float*)d_in[11];
    const float* W2 = (const float*)d_in[12];
    const float* b2 = (const float*)d_in[13];
    const float* g1 = (const float*)d_in[14];
    const float* be1= (const float*)d_in[15];
    const float* g2 = (const float*)d_in[16];
    const float* be2= (const float*)d_in[17];

    float *px, *pq, *pk, *pv, *po, *pffn;
    cudaGetSymbolAddress((void**)&px,   g_x);
    cudaGetSymbolAddress((void**)&pq,   g_q);
    cudaGetSymbolAddress((void**)&pk,   g_k);
    cudaGetSymbolAddress((void**)&pv,   g_v);
    cudaGetSymbolAddress((void**)&po,   g_o);
    cudaGetSymbolAddress((void**)&pffn, g_ffn);

    cudaMemcpyAsync(px, embeds, sizeof(float) * (size_t)ROWS * D_,
                    cudaMemcpyDeviceToDevice);

    const dim3 gD(D_ / 128, ROWS / 128);   // (8, 64)
    const dim3 gF(F_ / 128, ROWS / 128);   // (32, 64)
    const dim3 gA(M_ / 64, B_ * H_);       // (16, 128)

    for (int l = 0; l < NLAYERS; l++) {
        const float* wq = Wq + (size_t)l * D_ * D_;
        const float* wk = Wk + (size_t)l * D_ * D_;
        const float* wv = Wv + (size_t)l * D_ * D_;
        const float* wo = Wo + (size_t)l * D_ * D_;
        const float* w1 = W1 + (size_t)l * D_ * F_;
        const float* w2 = W2 + (size_t)l * F_ * D_;

        sgemm_bias<false><<<gD, 256>>>(px, wq, bq + (size_t)l * D_, pq, D_, D_);
        sgemm_bias<false><<<gD, 256>>>(px, wk, bk + (size_t)l * D_, pk, D_, D_);
        sgemm_bias<false><<<gD, 256>>>(px, wv, bv + (size_t)l * D_, pv, D_, D_);

        flash_attn<<<gA, 256>>>(pq, pk, pv, weights, pffn);

        sgemm_bias<false><<<gD, 256>>>(pffn, wo, bo + (size_t)l * D_, po, D_, D_);
        add_ln<<<ROWS, 256>>>(px, po, g1 + (size_t)l * D_, be1 + (size_t)l * D_, px);

        sgemm_bias<true><<<gF, 256>>>(px, w1, b1 + (size_t)l * F_, pffn, D_, F_);
        sgemm_bias<false><<<gD, 256>>>(pffn, w2, b2 + (size_t)l * D_, po, F_, D_);
        add_ln<<<ROWS, 256>>>(px, po, g2 + (size_t)l * D_, be2 + (size_t)l * D_, px);
    }

    cudaMemcpyAsync(d_out, px, sizeof(float) * (size_t)ROWS * D_,
                    cudaMemcpyDeviceToDevice);
}

// round 5
// speedup vs baseline: 1.1049x; 1.1049x over previous
#include <cuda_runtime.h>
#include <math.h>
#include <stdint.h>

#define B_ 8
#define M_ 1024
#define D_ 1024
#define H_ 16
#define F_ 4096
#define NLAYERS 4
#define DK_ 64
#define ROWS (B_*M_)

// ---------------- device scratch ----------------
__device__ float g_x  [ROWS * D_];
__device__ float g_xb [ROWS * D_];
__device__ float g_xs [ROWS * D_];
__device__ float g_q  [ROWS * D_];
__device__ float g_k  [ROWS * D_];
__device__ float g_v  [ROWS * D_];
__device__ float g_ob [ROWS * D_];
__device__ float g_os [ROWS * D_];
__device__ float g_res[ROWS * D_];
__device__ float g_fb [ROWS * F_];
__device__ float g_fs [ROWS * F_];
__device__ float g_wqb[NLAYERS*D_*D_]; __device__ float g_wqs[NLAYERS*D_*D_];
__device__ float g_wkb[NLAYERS*D_*D_]; __device__ float g_wks[NLAYERS*D_*D_];
__device__ float g_wvb[NLAYERS*D_*D_]; __device__ float g_wvs[NLAYERS*D_*D_];
__device__ float g_wob[NLAYERS*D_*D_]; __device__ float g_wos[NLAYERS*D_*D_];
__device__ float g_w1b[NLAYERS*D_*F_]; __device__ float g_w1s[NLAYERS*D_*F_];
__device__ float g_w2b[NLAYERS*F_*D_]; __device__ float g_w2s[NLAYERS*F_*D_];

// ---------------- helpers ----------------
__device__ __forceinline__ uint32_t smem_to_u32(const void* p) {
    uint32_t a;
    asm("{ .reg .u64 t; cvta.to.shared.u64 t, %1; cvt.u32.u64 %0, t; }" : "=r"(a) : "l"(p));
    return a;
}
__device__ __forceinline__ float tf32_rna(float x) {
    uint32_t r;
    asm("cvt.rna.tf32.f32 %0, %1;" : "=r"(r) : "f"(x));
    return __uint_as_float(r);
}
__device__ __forceinline__ float gelu_exact(float x) {
    return 0.5f * x * (1.0f + erff(x * 0.70710678118654752f));
}

#define CP_ASYNC16(dst, src) \
    asm volatile("cp.async.cg.shared.global [%0], [%1], 16;" :: "r"(dst), "l"(src))
#define CP_COMMIT() asm volatile("cp.async.commit_group;")
#define CP_WAIT(n)  asm volatile("cp.async.wait_group %0;" :: "n"(n))

#define MMA_TF32(d, a, b) \
    asm volatile("mma.sync.aligned.m16n8k8.row.col.f32.tf32.tf32.f32 " \
        "{%0,%1,%2,%3}, {%4,%5,%6,%7}, {%8,%9}, {%0,%1,%2,%3};" \
        : "+f"((d)[0]), "+f"((d)[1]), "+f"((d)[2]), "+f"((d)[3]) \
        : "r"((a)[0]), "r"((a)[1]), "r"((a)[2]), "r"((a)[3]), \
          "r"((b)[0]), "r"((b)[1]))

// ---------------- 3xTF32 GEMM via mma.sync ----------------
// C[m][n] = sum_k A[m][k] * Bt[n][k]; A, Bt given as tf32 big/small pairs.
// 128x128 CTA tile, 256 thr, warp tile 64x32, K-chunk 16, double buffer.
#define PAD 20
#define CHUNK 16
#define ARR_FLOATS (128 * PAD)                 // 2560 floats = 10240 B
#define STG_FLOATS (4 * ARR_FLOATS)            // Ab, As, Bb, Bs
#define GSMEM_BYTES (2 * STG_FLOATS * 4)       // 81920

template<bool GELU, bool WPLAIN, bool WSPLIT>
__global__ __launch_bounds__(256, 2) void gemm_mma(
    const float* __restrict__ Ab, const float* __restrict__ As,
    const float* __restrict__ Bb, const float* __restrict__ Bs,
    const float* __restrict__ bias,
    float* __restrict__ Cp, float* __restrict__ Cb, float* __restrict__ Cs,
    int K, int N)
{
    extern __shared__ float smem[];
    const int tid  = threadIdx.x;
    const int wid  = tid >> 5;
    const int lane = tid & 31;
    const int m0 = blockIdx.y * 128;
    const int n0 = blockIdx.x * 128;
    const int wm = wid & 1;          // 0..1 -> 64-row slab
    const int wn = wid >> 1;         // 0..3 -> 32-col slab
    const uint32_t sbase = smem_to_u32(smem);

    float acc[4][4][4];
#pragma unroll
    for (int i = 0; i < 4; i++)
#pragma unroll
        for (int j = 0; j < 4; j++)
#pragma unroll
            for (int r = 0; r < 4; r++) acc[i][j][r] = 0.0f;

    const int nch = K / CHUNK;

    // ---- async stage loader: 512 16B segs per array, 256 thr -> 2 each ----
    auto load_stage = [&](int stage, int kc) {
        const uint32_t st = sbase + (uint32_t)stage * STG_FLOATS * 4;
#pragma unroll
        for (int t = 0; t < 2; t++) {
            const int seg = tid + t * 256;       // 0..511
            const int row = seg >> 2;
            const int sg  = seg & 3;
            const uint32_t soff = (uint32_t)(row * PAD + sg * 4) * 4;
            const size_t  aoff = (size_t)(m0 + row) * K + kc + sg * 4;
            const size_t  boff = (size_t)(n0 + row) * K + kc + sg * 4;
            CP_ASYNC16(st + 0 * ARR_FLOATS * 4 + soff, Ab + aoff);
            CP_ASYNC16(st + 1 * ARR_FLOATS * 4 + soff, As + aoff);
            CP_ASYNC16(st + 2 * ARR_FLOATS * 4 + soff, Bb + boff);
            CP_ASYNC16(st + 3 * ARR_FLOATS * 4 + soff, Bs + boff);
        }
    };

    load_stage(0, 0);
    CP_COMMIT();

    const int lr = lane >> 2;   // 0..7
    const int lc = lane & 3;    // 0..3

    for (int c = 0; c < nch; c++) {
        if (c + 1 < nch) {
            load_stage((c + 1) & 1, (c + 1) * CHUNK);
            CP_COMMIT();
            CP_WAIT(1);
        } else {
            CP_WAIT(0);
        }
        __syncthreads();

        const float* sAb = smem + (size_t)(c & 1) * STG_FLOATS;
        const float* sAs = sAb + ARR_FLOATS;
        const float* sBb = sAb + 2 * ARR_FLOATS;
        const float* sBs = sAb + 3 * ARR_FLOATS;

#pragma unroll
        for (int ks = 0; ks < 2; ks++) {
            const int kc = ks * 8;
            uint32_t afb[4][4], afs[4][4];
#pragma unroll
            for (int i = 0; i < 4; i++) {
                const int base = (wm * 64 + i * 16 + lr) * PAD + kc + lc;
                afb[i][0] = __float_as_uint(sAb[base]);
                afb[i][1] = __float_as_uint(sAb[base + 8 * PAD]);
                afb[i][2] = __float_as_uint(sAb[base + 4]);
                afb[i][3] = __float_as_uint(sAb[base + 8 * PAD + 4]);
                afs[i][0] = __float_as_uint(sAs[base]);
                afs[i][1] = __float_as_uint(sAs[base + 8 * PAD]);
                afs[i][2] = __float_as_uint(sAs[base + 4]);
                afs[i][3] = __float_as_uint(sAs[base + 8 * PAD + 4]);
            }
            uint32_t bfb[4][2], bfs[4][2];
#pragma unroll
            for (int j = 0; j < 4; j++) {
                const int base = (wn * 32 + j * 8 + lr) * PAD + kc + lc;
                bfb[j][0] = __float_as_uint(sBb[base]);
                bfb[j][1] = __float_as_uint(sBb[base + 4]);
                bfs[j][0] = __float_as_uint(sBs[base]);
                bfs[j][1] = __float_as_uint(sBs[base + 4]);
            }
#pragma unroll
            for (int i = 0; i < 4; i++)
#pragma unroll
                for (int j = 0; j < 4; j++) {
                    MMA_TF32(acc[i][j], afb[i], bfb[j]);
                    MMA_TF32(acc[i][j], afb[i], bfs[j]);
                    MMA_TF32(acc[i][j], afs[i], bfb[j]);
                }
        }
        __syncthreads();
    }

    // ---- epilogue ----
#pragma unroll
    for (int i = 0; i < 4; i++) {
#pragma unroll
        for (int j = 0; j < 4; j++) {
            const int gr = m0 + wm * 64 + i * 16 + lr;
            const int gc = n0 + wn * 32 + j * 8 + lc * 2;
            const float b0 = bias[gc], b1 = bias[gc + 1];
#pragma unroll
            for (int half = 0; half < 2; half++) {
                const int row = gr + half * 8;
                float y0 = acc[i][j][half * 2 + 0] + b0;
                float y1 = acc[i][j][half * 2 + 1] + b1;
                if (GELU) { y0 = gelu_exact(y0); y1 = gelu_exact(y1); }
                const size_t o = (size_t)row * N + gc;
                if (WPLAIN) *(float2*)&Cp[o] = make_float2(y0, y1);
                if (WSPLIT) {
                    const float h0 = tf32_rna(y0), h1 = tf32_rna(y1);
                    *(float2*)&Cb[o] = make_float2(h0, h1);
                    *(float2*)&Cs[o] = make_float2(tf32_rna(y0 - h0), tf32_rna(y1 - h1));
                }
            }
        }
    }
}

// ---------------- weight split + transpose ----------------
// in: W[z][K][N] row-major -> out: T[z][N][K] tf32 big/small
__global__ __launch_bounds__(256) void wsplit_t(
    const float* __restrict__ W, float* __restrict__ Tb, float* __restrict__ Ts,
    int K, int N)
{
    __shared__ float t[32][33];
    const int n0 = blockIdx.x * 32, k0 = blockIdx.y * 32;
    const size_t zoff = (size_t)blockIdx.z * K * N;
    const int tx = threadIdx.x, ty = threadIdx.y;
#pragma unroll
    for (int r = ty; r < 32; r += 8)
        t[r][tx] = W[zoff + (size_t)(k0 + r) * N + n0 + tx];
    __syncthreads();
#pragma unroll
    for (int r = ty; r < 32; r += 8) {
        const float v = t[tx][r];
        const float hb = tf32_rna(v);
        const size_t o = zoff + (size_t)(n0 + r) * K + k0 + tx;
        Tb[o] = hb;
        Ts[o] = tf32_rna(v - hb);
    }
}

__global__ __launch_bounds__(1024) void split_x(
    const float* __restrict__ e, float* __restrict__ x,
    float* __restrict__ xb, float* __restrict__ xs)
{
    const size_t i = (size_t)blockIdx.x * 1024 + threadIdx.x;
    const float v = e[i];
    x[i] = v;
    const float hb = tf32_rna(v);
    xb[i] = hb;
    xs[i] = tf32_rna(v - hb);
}

// ---------------- flash attention (fp32 SIMT, split outputs) --------------
__global__ __launch_bounds__(256) void flash_attn(
    const float* __restrict__ q, const float* __restrict__ k,
    const float* __restrict__ v, const float* __restrict__ w,
    float* __restrict__ ob, float* __restrict__ os)
{
    __shared__ float Qs[64][68];
    __shared__ float Kt[64][68];
    __shared__ float Vs[64][68];
    __shared__ float Ps[64][68];

    const int b  = blockIdx.y >> 4;
    const int h  = blockIdx.y & 15;
    const int q0 = blockIdx.x * 64;
    const int tid = threadIdx.x;
    const int ty = tid >> 4;
    const int tx = tid & 15;
    const int hoff = h * DK_;

    const float* qbase = q + (size_t)b * M_ * D_ + hoff;
    const float* kbase = k + (size_t)b * M_ * D_ + hoff;
    const float* vbase = v + (size_t)b * M_ * D_ + hoff;
    const float* wbase = w + (size_t)b * M_;

    for (int idx = tid; idx < 64 * 64; idx += 256) {
        int r = idx >> 6, c = idx & 63;
        Qs[r][c] = qbase[(size_t)(q0 + r) * D_ + c];
    }

    float m_i[4], l_i[4], oacc[4][4];
#pragma unroll
    for (int i = 0; i < 4; i++) {
        m_i[i] = -1e30f; l_i[i] = 0.0f;
#pragma unroll
        for (int j = 0; j < 4; j++) oacc[i][j] = 0.0f;
    }
    __syncthreads();

    for (int kb = 0; kb < M_; kb += 64) {
        for (int idx = tid; idx < 64 * 64; idx += 256) {
            int r = idx >> 6, c = idx & 63;
            float kv = kbase[(size_t)(kb + r) * D_ + c];
            Kt[c][r] = kv;
            Vs[r][c] = vbase[(size_t)(kb + r) * D_ + c];
        }
        __syncthreads();

        float s[4][4];
#pragma unroll
        for (int i = 0; i < 4; i++)
#pragma unroll
            for (int j = 0; j < 4; j++) s[i][j] = 0.0f;

#pragma unroll 8
        for (int d = 0; d < 64; d++) {
            float a[4], bb[4];
#pragma unroll
            for (int i = 0; i < 4; i++) a[i] = Qs[ty * 4 + i][d];
#pragma unroll
            for (int j = 0; j < 4; j++) bb[j] = Kt[d][tx * 4 + j];
#pragma unroll
            for (int i = 0; i < 4; i++)
#pragma unroll
                for (int j = 0; j < 4; j++)
                    s[i][j] = fmaf(a[i], bb[j], s[i][j]);
        }

        float wj[4];
#pragma unroll
        for (int j = 0; j < 4; j++) wj[j] = wbase[kb + tx * 4 + j];
#pragma unroll
        for (int i = 0; i < 4; i++)
#pragma unroll
            for (int j = 0; j < 4; j++)
                s[i][j] = s[i][j] * 0.125f + wj[j];

#pragma unroll
        for (int i = 0; i < 4; i++) {
            float rmax = fmaxf(fmaxf(s[i][0], s[i][1]), fmaxf(s[i][2], s[i][3]));
#pragma unroll
            for (int off = 8; off > 0; off >>= 1)
                rmax = fmaxf(rmax, __shfl_xor_sync(0xffffffffu, rmax, off, 16));
            float mnew = fmaxf(m_i[i], rmax);
            float corr = __expf(m_i[i] - mnew);
            float rsum = 0.0f;
#pragma unroll
            for (int j = 0; j < 4; j++) {
                s[i][j] = __expf(s[i][j] - mnew);
                rsum += s[i][j];
            }
#pragma unroll
            for (int off = 8; off > 0; off >>= 1)
                rsum += __shfl_xor_sync(0xffffffffu, rsum, off, 16);
            l_i[i] = l_i[i] * corr + rsum;
            m_i[i] = mnew;
#pragma unroll
            for (int j = 0; j < 4; j++) oacc[i][j] *= corr;
#pragma unroll
            for (int j = 0; j < 4; j++) Ps[ty * 4 + i][tx * 4 + j] = s[i][j];
        }
        __syncthreads();

#pragma unroll 8
        for (int kk = 0; kk < 64; kk++) {
            float pr[4], vr[4];
#pragma unroll
            for (int i = 0; i < 4; i++) pr[i] = Ps[ty * 4 + i][kk];
#pragma unroll
            for (int j = 0; j < 4; j++) vr[j] = Vs[kk][tx * 4 + j];
#pragma unroll
            for (int i = 0; i < 4; i++)
#pragma unroll
                for (int j = 0; j < 4; j++)
                    oacc[i][j] = fmaf(pr[i], vr[j], oacc[i][j]);
        }
        __syncthreads();
    }

#pragma unroll
    for (int i = 0; i < 4; i++) {
        const float inv = 1.0f / l_i[i];
        const size_t base = (size_t)(b * M_ + q0 + ty * 4 + i) * D_ + hoff + tx * 4;
        float yb[4], ys[4];
#pragma unroll
        for (int j = 0; j < 4; j++) {
            const float y = oacc[i][j] * inv;
            const float hb = tf32_rna(y);
            yb[j] = hb;
            ys[j] = tf32_rna(y - hb);
        }
        *(float4*)&ob[base] = make_float4(yb[0], yb[1], yb[2], yb[3]);
        *(float4*)&os[base] = make_float4(ys[0], ys[1], ys[2], ys[3]);
    }
}

// ---------------- residual + LayerNorm (+split out) -----------------------
__device__ __forceinline__ float block_sum256(float val, float* red) {
    const int lane = threadIdx.x & 31;
    const int wid  = threadIdx.x >> 5;
#pragma unroll
    for (int o = 16; o > 0; o >>= 1) val += __shfl_xor_sync(0xffffffffu, val, o);
    if (lane == 0) red[wid] = val;
    __syncthreads();
    float t = (threadIdx.x < 8) ? red[threadIdx.x] : 0.0f;
    if (wid == 0) {
#pragma unroll
        for (int o = 4; o > 0; o >>= 1) t += __shfl_xor_sync(0xffffffffu, t, o);
        if (lane == 0) red[0] = t;
    }
    __syncthreads();
    float r = red[0];
    __syncthreads();
    return r;
}

__global__ __launch_bounds__(256) void add_ln(
    const float* __restrict__ xin, const float* __restrict__ del,
    const float* __restrict__ g, const float* __restrict__ be,
    float* __restrict__ xout, float* __restrict__ xb, float* __restrict__ xs)
{
    __shared__ float red[8];
    const int row = blockIdx.x;
    const int tid = threadIdx.x;
    const float* xr = xin + (size_t)row * D_;
    const float* dr = del + (size_t)row * D_;

    float v[4];
    float s = 0.0f;
#pragma unroll
    for (int u = 0; u < 4; u++) {
        v[u] = xr[tid + u * 256] + dr[tid + u * 256];
        s += v[u];
    }
    const float mu = block_sum256(s, red) * (1.0f / D_);
    float qs = 0.0f;
#pragma unroll
    for (int u = 0; u < 4; u++) {
        const float d = v[u] - mu;
        qs += d * d;
    }
    const float var = block_sum256(qs, red) * (1.0f / D_);
    const float rstd = rsqrtf(var + 1e-5f);
#pragma unroll
    for (int u = 0; u < 4; u++) {
        const int c = tid + u * 256;
        const size_t o = (size_t)row * D_ + c;
        const float y = (v[u] - mu) * rstd * g[c] + be[c];
        xout[o] = y;
        const float hb = tf32_rna(y);
        xb[o] = hb;
        xs[o] = tf32_rna(y - hb);
    }
}

// ---------------- host driver ----------------
extern "C" void kernel_launch(void* const* d_in, const int* in_sizes, int n_in,
                              void* d_out, int out_size) {
    const float* embeds  = (const float*)d_in[0];
    const float* weights = (const float*)d_in[1];
    const float* Wq = (const float*)d_in[2];
    const float* bq = (const float*)d_in[3];
    const float* Wk = (const float*)d_in[4];
    const float* bk = (const float*)d_in[5];
    const float* Wv = (const float*)d_in[6];
    const float* bv = (const float*)d_in[7];
    const float* Wo = (const float*)d_in[8];
    const float* bo = (const float*)d_in[9];
    const float* W1 = (const float*)d_in[10];
    const float* b1 = (const float*)d_in[11];
    const float* W2 = (const float*)d_in[12];
    const float* b2 = (const float*)d_in[13];
    const float* g1 = (const float*)d_in[14];
    const float* be1= (const float*)d_in[15];
    const float* g2 = (const float*)d_in[16];
    const float* be2= (const float*)d_in[17];

    float *px,*pxb,*pxs,*pq,*pk,*pv,*pob,*pos,*pres,*pfb,*pfs;
    float *pwqb,*pwqs,*pwkb,*pwks,*pwvb,*pwvs,*pwob,*pwos,*pw1b,*pw1s,*pw2b,*pw2s;
    cudaGetSymbolAddress((void**)&px,  g_x);
    cudaGetSymbolAddress((void**)&pxb, g_xb);
    cudaGetSymbolAddress((void**)&pxs, g_xs);
    cudaGetSymbolAddress((void**)&pq,  g_q);
    cudaGetSymbolAddress((void**)&pk,  g_k);
    cudaGetSymbolAddress((void**)&pv,  g_v);
    cudaGetSymbolAddress((void**)&pob, g_ob);
    cudaGetSymbolAddress((void**)&pos, g_os);
    cudaGetSymbolAddress((void**)&pres,g_res);
    cudaGetSymbolAddress((void**)&pfb, g_fb);
    cudaGetSymbolAddress((void**)&pfs, g_fs);
    cudaGetSymbolAddress((void**)&pwqb,g_wqb); cudaGetSymbolAddress((void**)&pwqs,g_wqs);
    cudaGetSymbolAddress((void**)&pwkb,g_wkb); cudaGetSymbolAddress((void**)&pwks,g_wks);
    cudaGetSymbolAddress((void**)&pwvb,g_wvb); cudaGetSymbolAddress((void**)&pwvs,g_wvs);
    cudaGetSymbolAddress((void**)&pwob,g_wob); cudaGetSymbolAddress((void**)&pwos,g_wos);
    cudaGetSymbolAddress((void**)&pw1b,g_w1b); cudaGetSymbolAddress((void**)&pw1s,g_w1s);
    cudaGetSymbolAddress((void**)&pw2b,g_w2b); cudaGetSymbolAddress((void**)&pw2s,g_w2s);

    cudaFuncSetAttribute(gemm_mma<false, true, false>,
                         cudaFuncAttributeMaxDynamicSharedMemorySize, GSMEM_BYTES);
    cudaFuncSetAttribute(gemm_mma<true, false, true>,
                         cudaFuncAttributeMaxDynamicSharedMemorySize, GSMEM_BYTES);

    wsplit_t<<<dim3(D_/32, D_/32, NLAYERS), dim3(32, 8)>>>(Wq, pwqb, pwqs, D_, D_);
    wsplit_t<<<dim3(D_/32, D_/32, NLAYERS), dim3(32, 8)>>>(Wk, pwkb, pwks, D_, D_);
    wsplit_t<<<dim3(D_/32, D_/32, NLAYERS), dim3(32, 8)>>>(Wv, pwvb, pwvs, D_, D_);
    wsplit_t<<<dim3(D_/32, D_/32, NLAYERS), dim3(32, 8)>>>(Wo, pwob, pwos, D_, D_);
    wsplit_t<<<dim3(F_/32, D_/32, NLAYERS), dim3(32, 8)>>>(W1, pw1b, pw1s, D_, F_);
    wsplit_t<<<dim3(D_/32, F_/32, NLAYERS), dim3(32, 8)>>>(W2, pw2b, pw2s, F_, D_);

    split_x<<<ROWS * D_ / 1024, 1024>>>(embeds, px, pxb, pxs);

    const dim3 gD(D_ / 128, ROWS / 128);   // (8, 64)
    const dim3 gF(F_ / 128, ROWS / 128);   // (32, 64)
    const dim3 gA(M_ / 64, B_ * H_);

    for (int l = 0; l < NLAYERS; l++) {
        gemm_mma<false, true, false><<<gD, 256, GSMEM_BYTES>>>(
            pxb, pxs, pwqb + (size_t)l*D_*D_, pwqs + (size_t)l*D_*D_,
            bq + (size_t)l*D_, pq, nullptr, nullptr, D_, D_);
        gemm_mma<false, true, false><<<gD, 256, GSMEM_BYTES>>>(
            pxb, pxs, pwkb + (size_t)l*D_*D_, pwks + (size_t)l*D_*D_,
            bk + (size_t)l*D_, pk, nullptr, nullptr, D_, D_);
        gemm_mma<false, true, false><<<gD, 256, GSMEM_BYTES>>>(
            pxb, pxs, pwvb + (size_t)l*D_*D_, pwvs + (size_t)l*D_*D_,
            bv + (size_t)l*D_, pv, nullptr, nullptr, D_, D_);

        flash_attn<<<gA, 256>>>(pq, pk, pv, weights, pob, pos);

        gemm_mma<false, true, false><<<gD, 256, GSMEM_BYTES>>>(
            pob, pos, pwob + (size_t)l*D_*D_, pwos + (size_t)l*D_*D_,
            bo + (size_t)l*D_, pres, nullptr, nullptr, D_, D_);
        add_ln<<<ROWS, 256>>>(px, pres, g1 + (size_t)l*D_, be1 + (size_t)l*D_,
                              px, pxb, pxs);

        gemm_mma<true, false, true><<<gF, 256, GSMEM_BYTES>>>(
            pxb, pxs, pw1b + (size_t)l*D_*F_, pw1s + (size_t)l*D_*F_,
            b1 + (size_t)l*F_, nullptr, pfb, pfs, D_, F_);
        gemm_mma<false, true, false><<<gD, 256, GSMEM_BYTES>>>(
            pfb, pfs, pw2b + (size_t)l*F_*D_, pw2s + (size_t)l*F_*D_,
            b2 + (size_t)l*D_, pres, nullptr, nullptr, F_, D_);
        add_ln<<<ROWS, 256>>>(px, pres, g2 + (size_t)l*D_, be2 + (size_t)l*D_,
                              px, pxb, pxs);
    }

    cudaMemcpyAsync(d_out, px, sizeof(float) * (size_t)ROWS * D_,
                    cudaMemcpyDeviceToDevice);
}

// round 6
// speedup vs baseline: 1.8042x; 1.6329x over previous
#include <cuda_runtime.h>
#include <cuda_bf16.h>
#include <math.h>
#include <stdint.h>

#define B_ 8
#define M_ 1024
#define D_ 1024
#define H_ 16
#define F_ 4096
#define NLAYERS 4
#define DK_ 64
#define ROWS (B_*M_)

typedef __nv_bfloat16 bf16;

// ---------------- device scratch ----------------
__device__ float g_x  [ROWS * D_];
__device__ float g_q  [ROWS * D_];
__device__ float g_k  [ROWS * D_];
__device__ float g_v  [ROWS * D_];
__device__ float g_res[ROWS * D_];
__device__ bf16  g_xb [ROWS * D_];
__device__ bf16  g_xs [ROWS * D_];
__device__ bf16  g_ob [ROWS * D_];
__device__ bf16  g_os [ROWS * D_];
__device__ bf16  g_fb [ROWS * F_];
__device__ bf16  g_fs [ROWS * F_];
__device__ bf16 g_wqb[NLAYERS*D_*D_]; __device__ bf16 g_wqs[NLAYERS*D_*D_];
__device__ bf16 g_wkb[NLAYERS*D_*D_]; __device__ bf16 g_wks[NLAYERS*D_*D_];
__device__ bf16 g_wvb[NLAYERS*D_*D_]; __device__ bf16 g_wvs[NLAYERS*D_*D_];
__device__ bf16 g_wob[NLAYERS*D_*D_]; __device__ bf16 g_wos[NLAYERS*D_*D_];
__device__ bf16 g_w1b[NLAYERS*D_*F_]; __device__ bf16 g_w1s[NLAYERS*D_*F_];
__device__ bf16 g_w2b[NLAYERS*F_*D_]; __device__ bf16 g_w2s[NLAYERS*F_*D_];

// ---------------- helpers ----------------
__device__ __forceinline__ uint32_t smem_to_u32(const void* p) {
    uint32_t a;
    asm("{ .reg .u64 t; cvta.to.shared.u64 t, %1; cvt.u32.u64 %0, t; }" : "=r"(a) : "l"(p));
    return a;
}
__device__ __forceinline__ float gelu_exact(float x) {
    return 0.5f * x * (1.0f + erff(x * 0.70710678118654752f));
}
__device__ __forceinline__ void split_bf(float y, bf16& b, bf16& s) {
    b = __float2bfloat16_rn(y);
    s = __float2bfloat16_rn(y - __bfloat162float(b));
}

#define CP_ASYNC16(dst, src) \
    asm volatile("cp.async.cg.shared.global [%0], [%1], 16;" :: "r"(dst), "l"(src))
#define CP_COMMIT() asm volatile("cp.async.commit_group;")
#define CP_WAIT(n)  asm volatile("cp.async.wait_group %0;" :: "n"(n))

#define MMA_BF16(d, a, b) \
    asm volatile("mma.sync.aligned.m16n8k16.row.col.f32.bf16.bf16.f32 " \
        "{%0,%1,%2,%3}, {%4,%5,%6,%7}, {%8,%9}, {%0,%1,%2,%3};" \
        : "+f"((d)[0]), "+f"((d)[1]), "+f"((d)[2]), "+f"((d)[3]) \
        : "r"((a)[0]), "r"((a)[1]), "r"((a)[2]), "r"((a)[3]), \
          "r"((b)[0]), "r"((b)[1]))

// ---------------- 3xBF16 GEMM via mma.sync.m16n8k16 ----------------
// C[m][n] = sum_k A[m][k]*Bt[n][k]; A,Bt given as bf16 big/small pairs.
// 128x128 CTA tile, 256 thr (8 warps, warp tile 64x32), K-chunk 32, dbl buffer.
#define CHUNK 32
#define RSU   20                       // row stride in uint32 (64B data + 16B pad)
#define ARR_U32 (128 * RSU)            // 2560 u32 = 10240 B per array
#define STG_U32 (4 * ARR_U32)          // Ab, As, Bb, Bs
#define GSMEM_BYTES (2 * STG_U32 * 4)  // 81920

template<bool GELU, bool WPLAIN, bool WSPLIT>
__global__ __launch_bounds__(256, 2) void gemm_mma(
    const bf16* __restrict__ Ab, const bf16* __restrict__ As,
    const bf16* __restrict__ Bb, const bf16* __restrict__ Bs,
    const float* __restrict__ bias,
    float* __restrict__ Cp, bf16* __restrict__ Cb, bf16* __restrict__ Cs,
    int K, int N)
{
    extern __shared__ uint32_t smem[];
    const int tid  = threadIdx.x;
    const int wid  = tid >> 5;
    const int lane = tid & 31;
    const int m0 = blockIdx.y * 128;
    const int n0 = blockIdx.x * 128;
    const int wm = wid & 1;          // 64-row slab
    const int wn = wid >> 1;         // 32-col slab
    const uint32_t sbase = smem_to_u32(smem);

    float acc[4][4][4];
#pragma unroll
    for (int i = 0; i < 4; i++)
#pragma unroll
        for (int j = 0; j < 4; j++)
#pragma unroll
            for (int r = 0; r < 4; r++) acc[i][j][r] = 0.0f;

    const int nch = K / CHUNK;

    // stage loader: per array 128 rows x 64B = 512 16B-segs; 256 thr -> 2 each
    auto load_stage = [&](int stage, int kc) {
        const uint32_t st = sbase + (uint32_t)stage * STG_U32 * 4;
#pragma unroll
        for (int t = 0; t < 2; t++) {
            const int seg = tid + t * 256;        // 0..511
            const int row = seg >> 2;
            const int q   = seg & 3;
            const uint32_t soff = (uint32_t)row * 80 + q * 16;
            const size_t  aoff = (size_t)(m0 + row) * K + kc + q * 8;
            const size_t  boff = (size_t)(n0 + row) * K + kc + q * 8;
            CP_ASYNC16(st + 0 * ARR_U32 * 4 + soff, Ab + aoff);
            CP_ASYNC16(st + 1 * ARR_U32 * 4 + soff, As + aoff);
            CP_ASYNC16(st + 2 * ARR_U32 * 4 + soff, Bb + boff);
            CP_ASYNC16(st + 3 * ARR_U32 * 4 + soff, Bs + boff);
        }
    };

    load_stage(0, 0);
    CP_COMMIT();

    const int lr = lane >> 2;   // 0..7
    const int lc = lane & 3;    // 0..3

    for (int c = 0; c < nch; c++) {
        if (c + 1 < nch) {
            load_stage((c + 1) & 1, (c + 1) * CHUNK);
            CP_COMMIT();
            CP_WAIT(1);
        } else {
            CP_WAIT(0);
        }
        __syncthreads();

        const uint32_t* sAb = smem + (size_t)(c & 1) * STG_U32;
        const uint32_t* sAs = sAb + ARR_U32;
        const uint32_t* sBb = sAb + 2 * ARR_U32;
        const uint32_t* sBs = sAb + 3 * ARR_U32;

#pragma unroll
        for (int ks = 0; ks < 2; ks++) {
            const int kc = ks * 8;               // in u32 units (16 halves)
            uint32_t afb[4][4], afs[4][4];
#pragma unroll
            for (int i = 0; i < 4; i++) {
                const int base = (wm * 64 + i * 16 + lr) * RSU + kc + lc;
                afb[i][0] = sAb[base];
                afb[i][1] = sAb[base + 8 * RSU];
                afb[i][2] = sAb[base + 4];
                afb[i][3] = sAb[base + 8 * RSU + 4];
                afs[i][0] = sAs[base];
                afs[i][1] = sAs[base + 8 * RSU];
                afs[i][2] = sAs[base + 4];
                afs[i][3] = sAs[base + 8 * RSU + 4];
            }
            uint32_t bfb[4][2], bfs[4][2];
#pragma unroll
            for (int j = 0; j < 4; j++) {
                const int base = (wn * 32 + j * 8 + lr) * RSU + kc + lc;
                bfb[j][0] = sBb[base];
                bfb[j][1] = sBb[base + 4];
                bfs[j][0] = sBs[base];
                bfs[j][1] = sBs[base + 4];
            }
#pragma unroll
            for (int i = 0; i < 4; i++)
#pragma unroll
                for (int j = 0; j < 4; j++) {
                    MMA_BF16(acc[i][j], afb[i], bfb[j]);
                    MMA_BF16(acc[i][j], afb[i], bfs[j]);
                    MMA_BF16(acc[i][j], afs[i], bfb[j]);
                }
        }
        __syncthreads();
    }

    // ---- epilogue ----
#pragma unroll
    for (int i = 0; i < 4; i++) {
#pragma unroll
        for (int j = 0; j < 4; j++) {
            const int gr = m0 + wm * 64 + i * 16 + lr;
            const int gc = n0 + wn * 32 + j * 8 + lc * 2;
            const float b0 = bias[gc], b1 = bias[gc + 1];
#pragma unroll
            for (int half = 0; half < 2; half++) {
                const int row = gr + half * 8;
                float y0 = acc[i][j][half * 2 + 0] + b0;
                float y1 = acc[i][j][half * 2 + 1] + b1;
                if (GELU) { y0 = gelu_exact(y0); y1 = gelu_exact(y1); }
                const size_t o = (size_t)row * N + gc;
                if (WPLAIN) *(float2*)&Cp[o] = make_float2(y0, y1);
                if (WSPLIT) {
                    bf16 hb0, hs0, hb1, hs1;
                    split_bf(y0, hb0, hs0);
                    split_bf(y1, hb1, hs1);
                    *(__nv_bfloat162*)&Cb[o] = __nv_bfloat162(hb0, hb1);
                    *(__nv_bfloat162*)&Cs[o] = __nv_bfloat162(hs0, hs1);
                }
            }
        }
    }
}

// ---------------- weight split + transpose ----------------
// in: W[z][K][N] row-major -> out: T[z][N][K] bf16 big/small
__global__ __launch_bounds__(256) void wsplit_t(
    const float* __restrict__ W, bf16* __restrict__ Tb, bf16* __restrict__ Ts,
    int K, int N)
{
    __shared__ float t[32][33];
    const int n0 = blockIdx.x * 32, k0 = blockIdx.y * 32;
    const size_t zoff = (size_t)blockIdx.z * K * N;
    const int tx = threadIdx.x, ty = threadIdx.y;
#pragma unroll
    for (int r = ty; r < 32; r += 8)
        t[r][tx] = W[zoff + (size_t)(k0 + r) * N + n0 + tx];
    __syncthreads();
#pragma unroll
    for (int r = ty; r < 32; r += 8) {
        const float v = t[tx][r];
        const size_t o = zoff + (size_t)(n0 + r) * K + k0 + tx;
        bf16 hb, hs;
        split_bf(v, hb, hs);
        Tb[o] = hb;
        Ts[o] = hs;
    }
}

__global__ __launch_bounds__(1024) void split_x(
    const float* __restrict__ e, float* __restrict__ x,
    bf16* __restrict__ xb, bf16* __restrict__ xs)
{
    const size_t i = (size_t)blockIdx.x * 1024 + threadIdx.x;
    const float v = e[i];
    x[i] = v;
    bf16 hb, hs;
    split_bf(v, hb, hs);
    xb[i] = hb;
    xs[i] = hs;
}

// ---------------- flash attention (fp32 SIMT, bf16-split outputs) ---------
__global__ __launch_bounds__(256) void flash_attn(
    const float* __restrict__ q, const float* __restrict__ k,
    const float* __restrict__ v, const float* __restrict__ w,
    bf16* __restrict__ ob, bf16* __restrict__ os)
{
    __shared__ float Qs[64][68];
    __shared__ float Kt[64][68];
    __shared__ float Vs[64][68];
    __shared__ float Ps[64][68];

    const int b  = blockIdx.y >> 4;
    const int h  = blockIdx.y & 15;
    const int q0 = blockIdx.x * 64;
    const int tid = threadIdx.x;
    const int ty = tid >> 4;
    const int tx = tid & 15;
    const int hoff = h * DK_;

    const float* qbase = q + (size_t)b * M_ * D_ + hoff;
    const float* kbase = k + (size_t)b * M_ * D_ + hoff;
    const float* vbase = v + (size_t)b * M_ * D_ + hoff;
    const float* wbase = w + (size_t)b * M_;

    for (int idx = tid; idx < 64 * 64; idx += 256) {
        int r = idx >> 6, c = idx & 63;
        Qs[r][c] = qbase[(size_t)(q0 + r) * D_ + c];
    }

    float m_i[4], l_i[4], oacc[4][4];
#pragma unroll
    for (int i = 0; i < 4; i++) {
        m_i[i] = -1e30f; l_i[i] = 0.0f;
#pragma unroll
        for (int j = 0; j < 4; j++) oacc[i][j] = 0.0f;
    }
    __syncthreads();

    for (int kb = 0; kb < M_; kb += 64) {
        for (int idx = tid; idx < 64 * 64; idx += 256) {
            int r = idx >> 6, c = idx & 63;
            float kv = kbase[(size_t)(kb + r) * D_ + c];
            Kt[c][r] = kv;
            Vs[r][c] = vbase[(size_t)(kb + r) * D_ + c];
        }
        __syncthreads();

        float s[4][4];
#pragma unroll
        for (int i = 0; i < 4; i++)
#pragma unroll
            for (int j = 0; j < 4; j++) s[i][j] = 0.0f;

#pragma unroll 8
        for (int d = 0; d < 64; d++) {
            float a[4], bb[4];
#pragma unroll
            for (int i = 0; i < 4; i++) a[i] = Qs[ty * 4 + i][d];
#pragma unroll
            for (int j = 0; j < 4; j++) bb[j] = Kt[d][tx * 4 + j];
#pragma unroll
            for (int i = 0; i < 4; i++)
#pragma unroll
                for (int j = 0; j < 4; j++)
                    s[i][j] = fmaf(a[i], bb[j], s[i][j]);
        }

        float wj[4];
#pragma unroll
        for (int j = 0; j < 4; j++) wj[j] = wbase[kb + tx * 4 + j];
#pragma unroll
        for (int i = 0; i < 4; i++)
#pragma unroll
            for (int j = 0; j < 4; j++)
                s[i][j] = s[i][j] * 0.125f + wj[j];

#pragma unroll
        for (int i = 0; i < 4; i++) {
            float rmax = fmaxf(fmaxf(s[i][0], s[i][1]), fmaxf(s[i][2], s[i][3]));
#pragma unroll
            for (int off = 8; off > 0; off >>= 1)
                rmax = fmaxf(rmax, __shfl_xor_sync(0xffffffffu, rmax, off, 16));
            float mnew = fmaxf(m_i[i], rmax);
            float corr = __expf(m_i[i] - mnew);
            float rsum = 0.0f;
#pragma unroll
            for (int j = 0; j < 4; j++) {
                s[i][j] = __expf(s[i][j] - mnew);
                rsum += s[i][j];
            }
#pragma unroll
            for (int off = 8; off > 0; off >>= 1)
                rsum += __shfl_xor_sync(0xffffffffu, rsum, off, 16);
            l_i[i] = l_i[i] * corr + rsum;
            m_i[i] = mnew;
#pragma unroll
            for (int j = 0; j < 4; j++) oacc[i][j] *= corr;
#pragma unroll
            for (int j = 0; j < 4; j++) Ps[ty * 4 + i][tx * 4 + j] = s[i][j];
        }
        __syncthreads();

#pragma unroll 8
        for (int kk = 0; kk < 64; kk++) {
            float pr[4], vr[4];
#pragma unroll
            for (int i = 0; i < 4; i++) pr[i] = Ps[ty * 4 + i][kk];
#pragma unroll
            for (int j = 0; j < 4; j++) vr[j] = Vs[kk][tx * 4 + j];
#pragma unroll
            for (int i = 0; i < 4; i++)
#pragma unroll
                for (int j = 0; j < 4; j++)
                    oacc[i][j] = fmaf(pr[i], vr[j], oacc[i][j]);
        }
        __syncthreads();
    }

#pragma unroll
    for (int i = 0; i < 4; i++) {
        const float inv = 1.0f / l_i[i];
        const size_t base = (size_t)(b * M_ + q0 + ty * 4 + i) * D_ + hoff + tx * 4;
#pragma unroll
        for (int jp = 0; jp < 2; jp++) {
            bf16 hb0, hs0, hb1, hs1;
            split_bf(oacc[i][jp * 2 + 0] * inv, hb0, hs0);
            split_bf(oacc[i][jp * 2 + 1] * inv, hb1, hs1);
            *(__nv_bfloat162*)&ob[base + jp * 2] = __nv_bfloat162(hb0, hb1);
            *(__nv_bfloat162*)&os[base + jp * 2] = __nv_bfloat162(hs0, hs1);
        }
    }
}

// ---------------- residual + LayerNorm (+bf16 split out) ------------------
__device__ __forceinline__ float block_sum256(float val, float* red) {
    const int lane = threadIdx.x & 31;
    const int wid  = threadIdx.x >> 5;
#pragma unroll
    for (int o = 16; o > 0; o >>= 1) val += __shfl_xor_sync(0xffffffffu, val, o);
    if (lane == 0) red[wid] = val;
    __syncthreads();
    float t = (threadIdx.x < 8) ? red[threadIdx.x] : 0.0f;
    if (wid == 0) {
#pragma unroll
        for (int o = 4; o > 0; o >>= 1) t += __shfl_xor_sync(0xffffffffu, t, o);
        if (lane == 0) red[0] = t;
    }
    __syncthreads();
    float r = red[0];
    __syncthreads();
    return r;
}

__global__ __launch_bounds__(256) void add_ln(
    const float* __restrict__ xin, const float* __restrict__ del,
    const float* __restrict__ g, const float* __restrict__ be,
    float* __restrict__ xout, bf16* __restrict__ xb, bf16* __restrict__ xs)
{
    __shared__ float red[8];
    const int row = blockIdx.x;
    const int tid = threadIdx.x;
    const float* xr = xin + (size_t)row * D_;
    const float* dr = del + (size_t)row * D_;

    float v[4];
    float s = 0.0f;
#pragma unroll
    for (int u = 0; u < 4; u++) {
        v[u] = xr[tid + u * 256] + dr[tid + u * 256];
        s += v[u];
    }
    const float mu = block_sum256(s, red) * (1.0f / D_);
    float qs = 0.0f;
#pragma unroll
    for (int u = 0; u < 4; u++) {
        const float d = v[u] - mu;
        qs += d * d;
    }
    const float var = block_sum256(qs, red) * (1.0f / D_);
    const float rstd = rsqrtf(var + 1e-5f);
#pragma unroll
    for (int u = 0; u < 4; u++) {
        const int c = tid + u * 256;
        const size_t o = (size_t)row * D_ + c;
        const float y = (v[u] - mu) * rstd * g[c] + be[c];
        xout[o] = y;
        bf16 hb, hs;
        split_bf(y, hb, hs);
        xb[o] = hb;
        xs[o] = hs;
    }
}

// ---------------- host driver ----------------
extern "C" void kernel_launch(void* const* d_in, const int* in_sizes, int n_in,
                              void* d_out, int out_size) {
    const float* embeds  = (const float*)d_in[0];
    const float* weights = (const float*)d_in[1];
    const float* Wq = (const float*)d_in[2];
    const float* bq = (const float*)d_in[3];
    const float* Wk = (const float*)d_in[4];
    const float* bk = (const float*)d_in[5];
    const float* Wv = (const float*)d_in[6];
    const float* bv = (const float*)d_in[7];
    const float* Wo = (const float*)d_in[8];
    const float* bo = (const float*)d_in[9];
    const float* W1 = (const float*)d_in[10];
    const float* b1 = (const float*)d_in[11];
    const float* W2 = (const float*)d_in[12];
    const float* b2 = (const float*)d_in[13];
    const float* g1 = (const float*)d_in[14];
    const float* be1= (const float*)d_in[15];
    const float* g2 = (const float*)d_in[16];
    const float* be2= (const float*)d_in[17];

    float *px,*pq,*pk,*pv,*pres;
    bf16 *pxb,*pxs,*pob,*pos,*pfb,*pfs;
    bf16 *pwqb,*pwqs,*pwkb,*pwks,*pwvb,*pwvs,*pwob,*pwos,*pw1b,*pw1s,*pw2b,*pw2s;
    cudaGetSymbolAddress((void**)&px,  g_x);
    cudaGetSymbolAddress((void**)&pq,  g_q);
    cudaGetSymbolAddress((void**)&pk,  g_k);
    cudaGetSymbolAddress((void**)&pv,  g_v);
    cudaGetSymbolAddress((void**)&pres,g_res);
    cudaGetSymbolAddress((void**)&pxb, g_xb);
    cudaGetSymbolAddress((void**)&pxs, g_xs);
    cudaGetSymbolAddress((void**)&pob, g_ob);
    cudaGetSymbolAddress((void**)&pos, g_os);
    cudaGetSymbolAddress((void**)&pfb, g_fb);
    cudaGetSymbolAddress((void**)&pfs, g_fs);
    cudaGetSymbolAddress((void**)&pwqb,g_wqb); cudaGetSymbolAddress((void**)&pwqs,g_wqs);
    cudaGetSymbolAddress((void**)&pwkb,g_wkb); cudaGetSymbolAddress((void**)&pwks,g_wks);
    cudaGetSymbolAddress((void**)&pwvb,g_wvb); cudaGetSymbolAddress((void**)&pwvs,g_wvs);
    cudaGetSymbolAddress((void**)&pwob,g_wob); cudaGetSymbolAddress((void**)&pwos,g_wos);
    cudaGetSymbolAddress((void**)&pw1b,g_w1b); cudaGetSymbolAddress((void**)&pw1s,g_w1s);
    cudaGetSymbolAddress((void**)&pw2b,g_w2b); cudaGetSymbolAddress((void**)&pw2s,g_w2s);

    cudaFuncSetAttribute(gemm_mma<false, true, false>,
                         cudaFuncAttributeMaxDynamicSharedMemorySize, GSMEM_BYTES);
    cudaFuncSetAttribute(gemm_mma<true, false, true>,
                         cudaFuncAttributeMaxDynamicSharedMemorySize, GSMEM_BYTES);

    wsplit_t<<<dim3(D_/32, D_/32, NLAYERS), dim3(32, 8)>>>(Wq, pwqb, pwqs, D_, D_);
    wsplit_t<<<dim3(D_/32, D_/32, NLAYERS), dim3(32, 8)>>>(Wk, pwkb, pwks, D_, D_);
    wsplit_t<<<dim3(D_/32, D_/32, NLAYERS), dim3(32, 8)>>>(Wv, pwvb, pwvs, D_, D_);
    wsplit_t<<<dim3(D_/32, D_/32, NLAYERS), dim3(32, 8)>>>(Wo, pwob, pwos, D_, D_);
    wsplit_t<<<dim3(F_/32, D_/32, NLAYERS), dim3(32, 8)>>>(W1, pw1b, pw1s, D_, F_);
    wsplit_t<<<dim3(D_/32, F_/32, NLAYERS), dim3(32, 8)>>>(W2, pw2b, pw2s, F_, D_);

    split_x<<<ROWS * D_ / 1024, 1024>>>(embeds, px, pxb, pxs);

    const dim3 gD(D_ / 128, ROWS / 128);   // (8, 64)
    const dim3 gF(F_ / 128, ROWS / 128);   // (32, 64)
    const dim3 gA(M_ / 64, B_ * H_);

    for (int l = 0; l < NLAYERS; l++) {
        gemm_mma<false, true, false><<<gD, 256, GSMEM_BYTES>>>(
            pxb, pxs, pwqb + (size_t)l*D_*D_, pwqs + (size_t)l*D_*D_,
            bq + (size_t)l*D_, pq, nullptr, nullptr, D_, D_);
        gemm_mma<false, true, false><<<gD, 256, GSMEM_BYTES>>>(
            pxb, pxs, pwkb + (size_t)l*D_*D_, pwks + (size_t)l*D_*D_,
            bk + (size_t)l*D_, pk, nullptr, nullptr, D_, D_);
        gemm_mma<false, true, false><<<gD, 256, GSMEM_BYTES>>>(
            pxb, pxs, pwvb + (size_t)l*D_*D_, pwvs + (size_t)l*D_*D_,
            bv + (size_t)l*D_, pv, nullptr, nullptr, D_, D_);

        flash_attn<<<gA, 256>>>(pq, pk, pv, weights, pob, pos);

        gemm_mma<false, true, false><<<gD, 256, GSMEM_BYTES>>>(
            pob, pos, pwob + (size_t)l*D_*D_, pwos + (size_t)l*D_*D_,
            bo + (size_t)l*D_, pres, nullptr, nullptr, D_, D_);
        add_ln<<<ROWS, 256>>>(px, pres, g1 + (size_t)l*D_, be1 + (size_t)l*D_,
                              px, pxb, pxs);

        gemm_mma<true, false, true><<<gF, 256, GSMEM_BYTES>>>(
            pxb, pxs, pw1b + (size_t)l*D_*F_, pw1s + (size_t)l*D_*F_,
            b1 + (size_t)l*F_, nullptr, pfb, pfs, D_, F_);
        gemm_mma<false, true, false><<<gD, 256, GSMEM_BYTES>>>(
            pfb, pfs, pw2b + (size_t)l*F_*D_, pw2s + (size_t)l*F_*D_,
            b2 + (size_t)l*D_, pres, nullptr, nullptr, F_, D_);
        add_ln<<<ROWS, 256>>>(px, pres, g2 + (size_t)l*D_, be2 + (size_t)l*D_,
                              px, pxb, pxs);
    }

    cudaMemcpyAsync(d_out, px, sizeof(float) * (size_t)ROWS * D_,
                    cudaMemcpyDeviceToDevice);
}